// round 5
// baseline (speedup 1.0000x reference)
#include <cuda_runtime.h>
#include <cuda_bf16.h>
#include <math.h>
#include <stdint.h>

#define EPS 1e-8f
#define TR  (1.0f/1024.0f)
#define TC  (1.0f/256.0f)
#define SEG 4194304            // 16*1024*256

// ---------------- scratch (device globals; no allocation) ----------------
__device__ float g_M[8388608];              // exp(sim/tau) fp32, [32768][256]
__device__ __nv_bfloat16 g_Mh[8388608];     // bf16 copy for sinkhorn iterations
__device__ __nv_bfloat16 g_pbh[131072];     // proto normalized, bf16 hi [2][256][256]
__device__ __nv_bfloat16 g_pbl[131072];     // proto normalized, bf16 lo
__device__ __nv_bfloat16 g_pth[131072];     // proto^T hi: [2][d][k]
__device__ __nv_bfloat16 g_ptl[131072];     // proto^T lo
__device__ float g_u[32768];
__device__ float g_v[8192];
__device__ float g_colacc[8192];
__device__ float g_csum2[8192];
__device__ float g_bs[32];

// exp(20*s) via 2^y, FFMA-only
__device__ __forceinline__ float exp20(float s) {
    float y  = s * 28.853900817779268f;
    float fl = floorf(y);
    float f  = y - fl;
    float p = 1.5252733804059840e-05f;
    p = fmaf(p, f, 1.5403530393381609e-04f);
    p = fmaf(p, f, 1.3333558146428443e-03f);
    p = fmaf(p, f, 9.6181291076284772e-03f);
    p = fmaf(p, f, 5.5504108664821580e-02f);
    p = fmaf(p, f, 2.4022650695910071e-01f);
    p = fmaf(p, f, 6.9314718055994531e-01f);
    p = fmaf(p, f, 1.0f);
    int e = (int)fl + 127;
    return p * __int_as_float(e << 23);
}

__device__ __forceinline__ uint32_t smem_u32(const void* p) {
    uint32_t a;
    asm("{ .reg .u64 t; cvta.to.shared.u64 t, %1; cvt.u32.u64 %0, t; }" : "=r"(a) : "l"(p));
    return a;
}
__device__ __forceinline__ void ldmx4(uint32_t* r, uint32_t addr) {
    asm volatile("ldmatrix.sync.aligned.m8n8.x4.shared.b16 {%0,%1,%2,%3}, [%4];"
                 : "=r"(r[0]), "=r"(r[1]), "=r"(r[2]), "=r"(r[3]) : "r"(addr));
}
__device__ __forceinline__ void mma16816(float* d, const uint32_t* a, const uint32_t* b) {
    asm volatile("mma.sync.aligned.m16n8k16.row.col.f32.bf16.bf16.f32 "
                 "{%0,%1,%2,%3}, {%4,%5,%6,%7}, {%8,%9}, {%0,%1,%2,%3};"
                 : "+f"(d[0]), "+f"(d[1]), "+f"(d[2]), "+f"(d[3])
                 : "r"(a[0]), "r"(a[1]), "r"(a[2]), "r"(a[3]), "r"(b[0]), "r"(b[1]));
}
__device__ __forceinline__ uint32_t pack_bf2(__nv_bfloat16 lo, __nv_bfloat16 hi) {
    __nv_bfloat162 t; t.x = lo; t.y = hi;
    uint32_t r; memcpy(&r, &t, 4); return r;
}
__device__ __forceinline__ void split_bf(float x, __nv_bfloat16& h, __nv_bfloat16& l) {
    h = __float2bfloat16_rn(x);
    l = __float2bfloat16_rn(x - __bfloat162float(h));
}

// ---------------- setup: zero accumulators + normalize/split/transpose protos ----------------
__global__ void k_proto(const float* __restrict__ p_rgb, const float* __restrict__ p_sn) {
    int gt = blockIdx.x * blockDim.x + threadIdx.x;    // 16384 threads
    if (gt < 8192) { g_colacc[gt] = 0.f; g_csum2[gt] = 0.f; }
    if (gt < 32)   g_bs[gt] = 0.f;

    int warp = gt >> 5;                                // 512 warps = [2][256] rows
    int lane = threadIdx.x & 31;
    int mod = warp >> 8, row = warp & 255;
    const float* src = (mod ? p_sn : p_rgb) + row * 256;
    float v[8], s = 0.f;
#pragma unroll
    for (int j = 0; j < 8; j++) { v[j] = src[lane + 32 * j]; s += v[j] * v[j]; }
#pragma unroll
    for (int o = 16; o; o >>= 1) s += __shfl_xor_sync(0xffffffffu, s, o);
    float inv = 1.0f / (sqrtf(s) + EPS);
    int base = mod * 65536;
#pragma unroll
    for (int j = 0; j < 8; j++) {
        int col = lane + 32 * j;
        float val = v[j] * inv;
        __nv_bfloat16 h, l;
        split_bf(val, h, l);
        g_pbh[base + row * 256 + col] = h;
        g_pbl[base + row * 256 + col] = l;
        g_pth[base + col * 256 + row] = h;   // transposed copy
        g_ptl[base + col * 256 + row] = l;
    }
}

// ---------------- shared MMA mainloop ----------------
// CTA tile 128x128, warp tile 32x64 (8 warps). K in 8 chunks of 32.
#define SROW 40

template <bool WANT_SS>
__device__ __forceinline__ void mma_mainloop(const float* __restrict__ A,
                                             const __nv_bfloat16* __restrict__ Bh,
                                             const __nv_bfloat16* __restrict__ Bl,
                                             float acc[2][8][4], int t, float* sSq) {
    __shared__ __nv_bfloat16 sAh[128 * SROW], sAl[128 * SROW];
    __shared__ __nv_bfloat16 sBh[128 * SROW], sBl[128 * SROW];
    int l = t & 31, w = t >> 5;
    int wm = w >> 1, wn = w & 1;

    uint32_t baseAh = smem_u32(sAh), baseAl = smem_u32(sAl);
    uint32_t baseBh = smem_u32(sBh), baseBl = smem_u32(sBl);

    uint32_t a_off = (uint32_t)(wm * 32 + (l & 7) + 8 * ((l >> 3) & 1)) * (SROW * 2)
                   + ((l >> 4) & 1) * 16;
    uint32_t b_off = (uint32_t)(wn * 64 + (l & 7) + 8 * ((l >> 4) & 1)) * (SROW * 2)
                   + ((l >> 3) & 1) * 16;

    float ss[4] = {0.f, 0.f, 0.f, 0.f};

    for (int c = 0; c < 8; c++) {
        int dd = c * 32;
#pragma unroll
        for (int i = 0; i < 4; i++) {
            int idx = t + 256 * i;
            int row = idx >> 3, c4 = idx & 7;
            float4 v = *(const float4*)(A + (size_t)row * 256 + dd + 4 * c4);
            if (WANT_SS)
                ss[i] += v.x * v.x + v.y * v.y + v.z * v.z + v.w * v.w;
            __nv_bfloat16 hx, lx, hy, ly, hz, lz, hw, lw;
            split_bf(v.x, hx, lx); split_bf(v.y, hy, ly);
            split_bf(v.z, hz, lz); split_bf(v.w, hw, lw);
            uint2 ph, pl;
            ph.x = pack_bf2(hx, hy); ph.y = pack_bf2(hz, hw);
            pl.x = pack_bf2(lx, ly); pl.y = pack_bf2(lz, lw);
            int so = row * SROW + 4 * c4;
            *(uint2*)(sAh + so) = ph;
            *(uint2*)(sAl + so) = pl;
        }
#pragma unroll
        for (int i = 0; i < 4; i++) {
            int idx = t + 256 * i;
            int part = idx >> 9, row = (idx >> 2) & 127, c8 = idx & 3;
            const __nv_bfloat16* src = part ? Bl : Bh;
            uint4 v = *(const uint4*)(src + (size_t)row * 256 + dd + 8 * c8);
            __nv_bfloat16* dst = part ? sBl : sBh;
            *(uint4*)(dst + row * SROW + 8 * c8) = v;
        }
        __syncthreads();
#pragma unroll
        for (int ks = 0; ks < 2; ks++) {
            uint32_t kb = ks * 32;
            uint32_t aH[2][4], aL[2][4];
            ldmx4(aH[0], baseAh + a_off + kb);
            ldmx4(aH[1], baseAh + a_off + 16 * (SROW * 2) + kb);
            ldmx4(aL[0], baseAl + a_off + kb);
            ldmx4(aL[1], baseAl + a_off + 16 * (SROW * 2) + kb);
#pragma unroll
            for (int np = 0; np < 4; np++) {
                uint32_t bo = b_off + (uint32_t)np * 16 * (SROW * 2) + kb;
                uint32_t bH[4], bL[4];
                ldmx4(bH, baseBh + bo);
                ldmx4(bL, baseBl + bo);
#pragma unroll
                for (int tm = 0; tm < 2; tm++) {
                    mma16816(acc[tm][2 * np],     aH[tm], bH);
                    mma16816(acc[tm][2 * np],     aH[tm], bL);
                    mma16816(acc[tm][2 * np],     aL[tm], bH);
                    mma16816(acc[tm][2 * np + 1], aH[tm], bH + 2);
                    mma16816(acc[tm][2 * np + 1], aH[tm], bL + 2);
                    mma16816(acc[tm][2 * np + 1], aL[tm], bH + 2);
                }
            }
        }
        __syncthreads();
    }
    if (WANT_SS) {
        // reduce across the 8 threads (c4=0..7) sharing each row
#pragma unroll
        for (int i = 0; i < 4; i++) {
            ss[i] += __shfl_xor_sync(0xffffffffu, ss[i], 1);
            ss[i] += __shfl_xor_sync(0xffffffffu, ss[i], 2);
            ss[i] += __shfl_xor_sync(0xffffffffu, ss[i], 4);
        }
        if ((t & 7) == 0) {
#pragma unroll
            for (int i = 0; i < 4; i++)
                sSq[(t >> 3) + 32 * i] = ss[i];
        }
        __syncthreads();
    }
}

// ---------------- GEMM1: sim = Xhat @ Phat^T ; M = exp(20*sim) (+xnorm fused) ----------------
__global__ __launch_bounds__(256, 2)
void k_gemm_sim(const float* __restrict__ f_rgb, const float* __restrict__ f_sn,
                float* __restrict__ out) {
    __shared__ float sSq[128];
    int t = threadIdx.x, l = t & 31, w = t >> 5;
    int wm = w >> 1, wn = w & 1;
    int bx = blockIdx.x;
    int row0 = (bx >> 1) * 128;
    int col0 = (bx & 1) * 128;
    int mod = row0 >> 14, lrow0 = row0 & 16383;
    const float* X = (mod ? f_sn : f_rgb) + (size_t)lrow0 * 256;
    const __nv_bfloat16* Bh = g_pbh + mod * 65536 + (size_t)col0 * 256;
    const __nv_bfloat16* Bl = g_pbl + mod * 65536 + (size_t)col0 * 256;

    float acc[2][8][4];
#pragma unroll
    for (int a = 0; a < 2; a++)
#pragma unroll
        for (int b = 0; b < 8; b++)
#pragma unroll
            for (int d = 0; d < 4; d++) acc[a][b][d] = 0.f;

    mma_mainloop<true>(X, Bh, Bl, acc, t, sSq);

    float* simb = out + (size_t)(4 + mod) * SEG;
    float psum = 0.f;
#pragma unroll
    for (int tm = 0; tm < 2; tm++) {
        int tr0 = wm * 32 + tm * 16 + (l >> 2);
        int r0 = row0 + tr0, r1 = r0 + 8;
        float xi0 = 1.0f / (sqrtf(sSq[tr0]) + EPS);
        float xi1 = 1.0f / (sqrtf(sSq[tr0 + 8]) + EPS);
        size_t lr0 = (size_t)(r0 & 16383) * 256, lr1 = (size_t)(r1 & 16383) * 256;
        size_t gr0 = (size_t)r0 * 256, gr1 = (size_t)r1 * 256;
#pragma unroll
        for (int nt = 0; nt < 8; nt++) {
            int col = col0 + wn * 64 + nt * 8 + 2 * (l & 3);
            float* d = acc[tm][nt];
            float2 s0 = {d[0] * xi0, d[1] * xi0};
            float2 s1 = {d[2] * xi1, d[3] * xi1};
            *(float2*)(simb + lr0 + col) = s0;
            *(float2*)(simb + lr1 + col) = s1;
            float2 e0 = {exp20(s0.x), exp20(s0.y)};
            float2 e1 = {exp20(s1.x), exp20(s1.y)};
            *(float2*)(g_M + gr0 + col) = e0;
            *(float2*)(g_M + gr1 + col) = e1;
            *(uint32_t*)(g_Mh + gr0 + col) = pack_bf2(__float2bfloat16_rn(e0.x),
                                                      __float2bfloat16_rn(e0.y));
            *(uint32_t*)(g_Mh + gr1 + col) = pack_bf2(__float2bfloat16_rn(e1.x),
                                                      __float2bfloat16_rn(e1.y));
            psum += (e0.x + e0.y) + (e1.x + e1.y);
        }
    }
#pragma unroll
    for (int o = 16; o; o >>= 1) psum += __shfl_xor_sync(0xffffffffu, psum, o);
    if (l == 0) atomicAdd(&g_bs[row0 >> 10], psum);
}

// ---------------- sinkhorn iteration, bf16 M, single pass ----------------
__global__ __launch_bounds__(256)
void k_sink_row(int first) {
    __shared__ float vs[256];
    __shared__ float colacc[256];
    int t = threadIdx.x, lane = t & 31, w = t >> 5;
    int row0 = blockIdx.x * 64;
    int bm = row0 >> 10;
    vs[t] = first ? 1.0f : g_v[bm * 256 + t];
    colacc[t] = 0.f;
    __syncthreads();
    float u_init = first ? 1.0f / (g_bs[bm] + EPS) : 0.f;
    float vr[8];
#pragma unroll
    for (int j = 0; j < 8; j++) vr[j] = vs[8 * lane + j];
    float c[8] = {0, 0, 0, 0, 0, 0, 0, 0};
#pragma unroll
    for (int r = 0; r < 8; r++) {
        int n = row0 + w * 8 + r;
        uint4 mv = *(const uint4*)(g_Mh + (size_t)n * 256 + 8 * lane);
        float m[8];
        {
            float2 f;
            f = __bfloat1622float2(*(__nv_bfloat162*)&mv.x); m[0] = f.x; m[1] = f.y;
            f = __bfloat1622float2(*(__nv_bfloat162*)&mv.y); m[2] = f.x; m[3] = f.y;
            f = __bfloat1622float2(*(__nv_bfloat162*)&mv.z); m[4] = f.x; m[5] = f.y;
            f = __bfloat1622float2(*(__nv_bfloat162*)&mv.w); m[6] = f.x; m[7] = f.y;
        }
        float dot = 0.f;
#pragma unroll
        for (int j = 0; j < 8; j++) dot = fmaf(m[j], vr[j], dot);
#pragma unroll
        for (int o = 16; o; o >>= 1) dot += __shfl_xor_sync(0xffffffffu, dot, o);
        float u = first ? u_init : g_u[n];
        float un = u * TR / (u * dot + EPS);
        if (lane == 0) g_u[n] = un;
#pragma unroll
        for (int j = 0; j < 8; j++) c[j] = fmaf(m[j], un, c[j]);
    }
#pragma unroll
    for (int j = 0; j < 8; j++) atomicAdd(&colacc[8 * lane + j], c[j]);
    __syncthreads();
    atomicAdd(&g_colacc[bm * 256 + t], colacc[t]);
}

__global__ void k_sink_col(int first) {
    int i = blockIdx.x * blockDim.x + threadIdx.x;
    if (i < 8192) {
        float v = first ? 1.0f : g_v[i];
        float a = g_colacc[i];
        g_v[i] = v * TC / (v * a + EPS);
        g_colacc[i] = 0.f;
    }
}

// ---------------- final row-normalize (fp32 M), write assign, colsums ----------------
__global__ __launch_bounds__(256)
void k_final(float* __restrict__ out) {
    __shared__ float vs[256];
    __shared__ float colacc[256];
    int t = threadIdx.x, lane = t & 31, w = t >> 5;
    int row0 = blockIdx.x * 64;
    int bm = row0 >> 10;
    int mod = row0 >> 14;
    vs[t] = g_v[bm * 256 + t];
    colacc[t] = 0.f;
    __syncthreads();
    float4 vr0 = *(const float4*)&vs[4 * lane];
    float4 vr1 = *(const float4*)&vs[128 + 4 * lane];
    float4 c0 = {0, 0, 0, 0}, c1 = {0, 0, 0, 0};
    float* aout = out + (size_t)(2 + mod) * SEG;
#pragma unroll
    for (int r = 0; r < 8; r++) {
        int n = row0 + w * 8 + r;
        int lrow = n & 16383;
        const float4* Mr = (const float4*)(g_M + (size_t)n * 256);
        float4 m0 = Mr[lane], m1 = Mr[32 + lane];
        float dot = m0.x * vr0.x + m0.y * vr0.y + m0.z * vr0.z + m0.w * vr0.w
                  + m1.x * vr1.x + m1.y * vr1.y + m1.z * vr1.z + m1.w * vr1.w;
#pragma unroll
        for (int o = 16; o; o >>= 1) dot += __shfl_xor_sync(0xffffffffu, dot, o);
        float u = g_u[n];
        float un = u / (u * dot + EPS);
        float4 a0, a1;
        a0.x = m0.x * un * vr0.x; a0.y = m0.y * un * vr0.y;
        a0.z = m0.z * un * vr0.z; a0.w = m0.w * un * vr0.w;
        a1.x = m1.x * un * vr1.x; a1.y = m1.y * un * vr1.y;
        a1.z = m1.z * un * vr1.z; a1.w = m1.w * un * vr1.w;
        *(float4*)(aout + (size_t)lrow * 256 + 4 * lane) = a0;
        *(float4*)(aout + (size_t)lrow * 256 + 128 + 4 * lane) = a1;
        c0.x += a0.x; c0.y += a0.y; c0.z += a0.z; c0.w += a0.w;
        c1.x += a1.x; c1.y += a1.y; c1.z += a1.z; c1.w += a1.w;
    }
    atomicAdd(&colacc[4 * lane + 0], c0.x); atomicAdd(&colacc[4 * lane + 1], c0.y);
    atomicAdd(&colacc[4 * lane + 2], c0.z); atomicAdd(&colacc[4 * lane + 3], c0.w);
    atomicAdd(&colacc[128 + 4 * lane + 0], c1.x); atomicAdd(&colacc[128 + 4 * lane + 1], c1.y);
    atomicAdd(&colacc[128 + 4 * lane + 2], c1.z); atomicAdd(&colacc[128 + 4 * lane + 3], c1.w);
    __syncthreads();
    atomicAdd(&g_csum2[bm * 256 + t], colacc[t]);
}

// ---------------- GEMM2: z = assign @ Phat (+consistency fused into block 0) ----------------
__global__ __launch_bounds__(256, 2)
void k_gemm_z(float* __restrict__ out) {
    int t = threadIdx.x, l = t & 31, w = t >> 5;
    int wm = w >> 1, wn = w & 1;
    int bx = blockIdx.x;
    int row0 = (bx >> 1) * 128;
    int col0 = (bx & 1) * 128;
    int mod = row0 >> 14, lrow0 = row0 & 16383;
    const float* A = out + (size_t)(2 + mod) * SEG + (size_t)lrow0 * 256;
    const __nv_bfloat16* Bh = g_pth + mod * 65536 + (size_t)col0 * 256;
    const __nv_bfloat16* Bl = g_ptl + mod * 65536 + (size_t)col0 * 256;

    float acc[2][8][4];
#pragma unroll
    for (int a = 0; a < 2; a++)
#pragma unroll
        for (int b = 0; b < 8; b++)
#pragma unroll
            for (int d = 0; d < 4; d++) acc[a][b][d] = 0.f;

    mma_mainloop<false>(A, Bh, Bl, acc, t, nullptr);

    float* zb = out + (size_t)mod * SEG;
#pragma unroll
    for (int tm = 0; tm < 2; tm++) {
        int r0 = row0 + wm * 32 + tm * 16 + (l >> 2);
        size_t lr0 = (size_t)(r0 & 16383) * 256, lr1 = lr0 + 8 * 256;
#pragma unroll
        for (int nt = 0; nt < 8; nt++) {
            int col = col0 + wn * 64 + nt * 8 + 2 * (l & 3);
            float* d = acc[tm][nt];
            float2 v0 = {d[0], d[1]}, v1 = {d[2], d[3]};
            *(float2*)(zb + lr0 + col) = v0;
            *(float2*)(zb + lr1 + col) = v1;
        }
    }

    // sem_consistency, computed once by block 0
    if (bx == 0) {
        __shared__ float red[8];
        float accs = 0.f;
#pragma unroll
        for (int b = 0; b < 16; b++)
            accs += g_csum2[b * 256 + t] * g_csum2[4096 + b * 256 + t];
#pragma unroll
        for (int o = 16; o; o >>= 1) accs += __shfl_xor_sync(0xffffffffu, accs, o);
        if (l == 0) red[w] = accs;
        __syncthreads();
        if (t == 0) {
            float tot = 0.f;
            for (int i = 0; i < 8; i++) tot += red[i];
            float m = tot * (1.0f / 16777216.0f);
            m = fminf(fmaxf(m, 0.f), 1.f);
            out[(size_t)6 * SEG] = 1.0f - m;
        }
    }
}

// ---------------- launch ----------------
extern "C" void kernel_launch(void* const* d_in, const int* in_sizes, int n_in,
                              void* d_out, int out_size) {
    const float* f_rgb = (const float*)d_in[0];
    const float* f_sn  = (const float*)d_in[1];
    const float* p_rgb = (const float*)d_in[2];
    const float* p_sn  = (const float*)d_in[3];
    float* out = (float*)d_out;

    k_proto<<<64, 256>>>(p_rgb, p_sn);
    k_gemm_sim<<<512, 256>>>(f_rgb, f_sn, out);
    for (int it = 0; it < 5; it++) {
        k_sink_row<<<512, 256>>>(it == 0);
        k_sink_col<<<32, 256>>>(it == 0);
    }
    k_final<<<512, 256>>>(out);
    k_gemm_z<<<512, 256>>>(out);
}

// round 6
// speedup vs baseline: 1.0294x; 1.0294x over previous
#include <cuda_runtime.h>
#include <cuda_bf16.h>
#include <math.h>
#include <stdint.h>

#define EPS 1e-8f
#define TR  (1.0f/1024.0f)
#define TC  (1.0f/256.0f)
#define SEG 4194304            // 16*1024*256

// ---------------- scratch (device globals; no allocation) ----------------
__device__ float g_M[8388608];              // exp(sim/tau) fp32, [32768][256]
__device__ __nv_bfloat16 g_Mh[8388608];     // bf16 copy for sinkhorn iterations
__device__ __nv_bfloat16 g_pbh[131072];     // proto normalized, bf16 hi [2][256][256]
__device__ __nv_bfloat16 g_pbl[131072];     // proto normalized, bf16 lo
__device__ __nv_bfloat16 g_pth[131072];     // proto^T hi: [2][d][k]
__device__ __nv_bfloat16 g_ptl[131072];     // proto^T lo
__device__ float g_u[32768];
__device__ float g_v[8192];
__device__ float g_csum2[8192];
__device__ float g_bs[32];

// exp(20*s) via 2^y, FFMA-only
__device__ __forceinline__ float exp20(float s) {
    float y  = s * 28.853900817779268f;
    float fl = floorf(y);
    float f  = y - fl;
    float p = 1.5252733804059840e-05f;
    p = fmaf(p, f, 1.5403530393381609e-04f);
    p = fmaf(p, f, 1.3333558146428443e-03f);
    p = fmaf(p, f, 9.6181291076284772e-03f);
    p = fmaf(p, f, 5.5504108664821580e-02f);
    p = fmaf(p, f, 2.4022650695910071e-01f);
    p = fmaf(p, f, 6.9314718055994531e-01f);
    p = fmaf(p, f, 1.0f);
    int e = (int)fl + 127;
    return p * __int_as_float(e << 23);
}

__device__ __forceinline__ uint32_t smem_u32(const void* p) {
    uint32_t a;
    asm("{ .reg .u64 t; cvta.to.shared.u64 t, %1; cvt.u32.u64 %0, t; }" : "=r"(a) : "l"(p));
    return a;
}
__device__ __forceinline__ void ldmx4(uint32_t* r, uint32_t addr) {
    asm volatile("ldmatrix.sync.aligned.m8n8.x4.shared.b16 {%0,%1,%2,%3}, [%4];"
                 : "=r"(r[0]), "=r"(r[1]), "=r"(r[2]), "=r"(r[3]) : "r"(addr));
}
__device__ __forceinline__ void mma16816(float* d, const uint32_t* a, const uint32_t* b) {
    asm volatile("mma.sync.aligned.m16n8k16.row.col.f32.bf16.bf16.f32 "
                 "{%0,%1,%2,%3}, {%4,%5,%6,%7}, {%8,%9}, {%0,%1,%2,%3};"
                 : "+f"(d[0]), "+f"(d[1]), "+f"(d[2]), "+f"(d[3])
                 : "r"(a[0]), "r"(a[1]), "r"(a[2]), "r"(a[3]), "r"(b[0]), "r"(b[1]));
}
__device__ __forceinline__ uint32_t pack_bf2(__nv_bfloat16 lo, __nv_bfloat16 hi) {
    __nv_bfloat162 t; t.x = lo; t.y = hi;
    uint32_t r; memcpy(&r, &t, 4); return r;
}
__device__ __forceinline__ void split_bf(float x, __nv_bfloat16& h, __nv_bfloat16& l) {
    h = __float2bfloat16_rn(x);
    l = __float2bfloat16_rn(x - __bfloat162float(h));
}

// ---------------- setup: zero accumulators + normalize/split/transpose protos ----------------
__global__ void k_proto(const float* __restrict__ p_rgb, const float* __restrict__ p_sn) {
    int gt = blockIdx.x * blockDim.x + threadIdx.x;    // 16384 threads
    if (gt < 8192) g_csum2[gt] = 0.f;
    if (gt < 32)   g_bs[gt] = 0.f;

    int warp = gt >> 5;
    int lane = threadIdx.x & 31;
    int mod = warp >> 8, row = warp & 255;
    const float* src = (mod ? p_sn : p_rgb) + row * 256;
    float v[8], s = 0.f;
#pragma unroll
    for (int j = 0; j < 8; j++) { v[j] = src[lane + 32 * j]; s += v[j] * v[j]; }
#pragma unroll
    for (int o = 16; o; o >>= 1) s += __shfl_xor_sync(0xffffffffu, s, o);
    float inv = 1.0f / (sqrtf(s) + EPS);
    int base = mod * 65536;
#pragma unroll
    for (int j = 0; j < 8; j++) {
        int col = lane + 32 * j;
        float val = v[j] * inv;
        __nv_bfloat16 h, l;
        split_bf(val, h, l);
        g_pbh[base + row * 256 + col] = h;
        g_pbl[base + row * 256 + col] = l;
        g_pth[base + col * 256 + row] = h;
        g_ptl[base + col * 256 + row] = l;
    }
}

// ---------------- shared MMA mainloop (proven round-4/5 structure) ----------------
#define SROW 40

template <bool WANT_SS>
__device__ __forceinline__ void mma_mainloop(const float* __restrict__ A,
                                             const __nv_bfloat16* __restrict__ Bh,
                                             const __nv_bfloat16* __restrict__ Bl,
                                             float acc[2][8][4], int t, float* sSq) {
    __shared__ __nv_bfloat16 sAh[128 * SROW], sAl[128 * SROW];
    __shared__ __nv_bfloat16 sBh[128 * SROW], sBl[128 * SROW];
    int l = t & 31, w = t >> 5;
    int wm = w >> 1, wn = w & 1;

    uint32_t baseAh = smem_u32(sAh), baseAl = smem_u32(sAl);
    uint32_t baseBh = smem_u32(sBh), baseBl = smem_u32(sBl);

    uint32_t a_off = (uint32_t)(wm * 32 + (l & 7) + 8 * ((l >> 3) & 1)) * (SROW * 2)
                   + ((l >> 4) & 1) * 16;
    uint32_t b_off = (uint32_t)(wn * 64 + (l & 7) + 8 * ((l >> 4) & 1)) * (SROW * 2)
                   + ((l >> 3) & 1) * 16;

    float ss[4] = {0.f, 0.f, 0.f, 0.f};

    for (int c = 0; c < 8; c++) {
        int dd = c * 32;
#pragma unroll
        for (int i = 0; i < 4; i++) {
            int idx = t + 256 * i;
            int row = idx >> 3, c4 = idx & 7;
            float4 v = *(const float4*)(A + (size_t)row * 256 + dd + 4 * c4);
            if (WANT_SS)
                ss[i] += v.x * v.x + v.y * v.y + v.z * v.z + v.w * v.w;
            __nv_bfloat16 hx, lx, hy, ly, hz, lz, hw, lw;
            split_bf(v.x, hx, lx); split_bf(v.y, hy, ly);
            split_bf(v.z, hz, lz); split_bf(v.w, hw, lw);
            uint2 ph, pl;
            ph.x = pack_bf2(hx, hy); ph.y = pack_bf2(hz, hw);
            pl.x = pack_bf2(lx, ly); pl.y = pack_bf2(lz, lw);
            int so = row * SROW + 4 * c4;
            *(uint2*)(sAh + so) = ph;
            *(uint2*)(sAl + so) = pl;
        }
#pragma unroll
        for (int i = 0; i < 4; i++) {
            int idx = t + 256 * i;
            int part = idx >> 9, row = (idx >> 2) & 127, c8 = idx & 3;
            const __nv_bfloat16* src = part ? Bl : Bh;
            uint4 v = *(const uint4*)(src + (size_t)row * 256 + dd + 8 * c8);
            __nv_bfloat16* dst = part ? sBl : sBh;
            *(uint4*)(dst + row * SROW + 8 * c8) = v;
        }
        __syncthreads();
#pragma unroll
        for (int ks = 0; ks < 2; ks++) {
            uint32_t kb = ks * 32;
            uint32_t aH[2][4], aL[2][4];
            ldmx4(aH[0], baseAh + a_off + kb);
            ldmx4(aH[1], baseAh + a_off + 16 * (SROW * 2) + kb);
            ldmx4(aL[0], baseAl + a_off + kb);
            ldmx4(aL[1], baseAl + a_off + 16 * (SROW * 2) + kb);
#pragma unroll
            for (int np = 0; np < 4; np++) {
                uint32_t bo = b_off + (uint32_t)np * 16 * (SROW * 2) + kb;
                uint32_t bH[4], bL[4];
                ldmx4(bH, baseBh + bo);
                ldmx4(bL, baseBl + bo);
#pragma unroll
                for (int tm = 0; tm < 2; tm++) {
                    mma16816(acc[tm][2 * np],     aH[tm], bH);
                    mma16816(acc[tm][2 * np],     aH[tm], bL);
                    mma16816(acc[tm][2 * np],     aL[tm], bH);
                    mma16816(acc[tm][2 * np + 1], aH[tm], bH + 2);
                    mma16816(acc[tm][2 * np + 1], aH[tm], bL + 2);
                    mma16816(acc[tm][2 * np + 1], aL[tm], bH + 2);
                }
            }
        }
        __syncthreads();
    }
    if (WANT_SS) {
#pragma unroll
        for (int i = 0; i < 4; i++) {
            ss[i] += __shfl_xor_sync(0xffffffffu, ss[i], 1);
            ss[i] += __shfl_xor_sync(0xffffffffu, ss[i], 2);
            ss[i] += __shfl_xor_sync(0xffffffffu, ss[i], 4);
        }
        if ((t & 7) == 0) {
#pragma unroll
            for (int i = 0; i < 4; i++)
                sSq[(t >> 3) + 32 * i] = ss[i];
        }
        __syncthreads();
    }
}

// ---------------- GEMM1: sim = Xhat @ Phat^T ; M = exp(20*sim) (+xnorm fused) ----------------
__global__ __launch_bounds__(256, 2)
void k_gemm_sim(const float* __restrict__ f_rgb, const float* __restrict__ f_sn,
                float* __restrict__ out) {
    __shared__ float sSq[128];
    int t = threadIdx.x, l = t & 31, w = t >> 5;
    int wm = w >> 1, wn = w & 1;
    int bx = blockIdx.x;
    int row0 = (bx >> 1) * 128;
    int col0 = (bx & 1) * 128;
    int mod = row0 >> 14, lrow0 = row0 & 16383;
    const float* X = (mod ? f_sn : f_rgb) + (size_t)lrow0 * 256;
    const __nv_bfloat16* Bh = g_pbh + mod * 65536 + (size_t)col0 * 256;
    const __nv_bfloat16* Bl = g_pbl + mod * 65536 + (size_t)col0 * 256;

    float acc[2][8][4];
#pragma unroll
    for (int a = 0; a < 2; a++)
#pragma unroll
        for (int b = 0; b < 8; b++)
#pragma unroll
            for (int d = 0; d < 4; d++) acc[a][b][d] = 0.f;

    mma_mainloop<true>(X, Bh, Bl, acc, t, sSq);

    float* simb = out + (size_t)(4 + mod) * SEG;
    float psum = 0.f;
#pragma unroll
    for (int tm = 0; tm < 2; tm++) {
        int tr0 = wm * 32 + tm * 16 + (l >> 2);
        int r0 = row0 + tr0, r1 = r0 + 8;
        float xi0 = 1.0f / (sqrtf(sSq[tr0]) + EPS);
        float xi1 = 1.0f / (sqrtf(sSq[tr0 + 8]) + EPS);
        size_t lr0 = (size_t)(r0 & 16383) * 256, lr1 = (size_t)(r1 & 16383) * 256;
        size_t gr0 = (size_t)r0 * 256, gr1 = (size_t)r1 * 256;
#pragma unroll
        for (int nt = 0; nt < 8; nt++) {
            int col = col0 + wn * 64 + nt * 8 + 2 * (l & 3);
            float* d = acc[tm][nt];
            float2 s0 = {d[0] * xi0, d[1] * xi0};
            float2 s1 = {d[2] * xi1, d[3] * xi1};
            *(float2*)(simb + lr0 + col) = s0;
            *(float2*)(simb + lr1 + col) = s1;
            float2 e0 = {exp20(s0.x), exp20(s0.y)};
            float2 e1 = {exp20(s1.x), exp20(s1.y)};
            *(float2*)(g_M + gr0 + col) = e0;
            *(float2*)(g_M + gr1 + col) = e1;
            *(uint32_t*)(g_Mh + gr0 + col) = pack_bf2(__float2bfloat16_rn(e0.x),
                                                      __float2bfloat16_rn(e0.y));
            *(uint32_t*)(g_Mh + gr1 + col) = pack_bf2(__float2bfloat16_rn(e1.x),
                                                      __float2bfloat16_rn(e1.y));
            psum += (e0.x + e0.y) + (e1.x + e1.y);
        }
    }
#pragma unroll
    for (int o = 16; o; o >>= 1) psum += __shfl_xor_sync(0xffffffffu, psum, o);
    if (l == 0) atomicAdd(&g_bs[row0 >> 10], psum);
}

// ---------------- full sinkhorn (5 iters) in ONE launch: CTA per (mod,batch) slice ----------------
__global__ __launch_bounds__(512, 1)
void k_sinkhorn() {
    __shared__ float su[1024];
    __shared__ float sv[256];
    __shared__ float scol[256];
    int t = threadIdx.x, lane = t & 31, w = t >> 5;    // 16 warps
    int bm = blockIdx.x;                               // 0..31
    const __nv_bfloat16* Mb = g_Mh + (size_t)bm * 262144;

    float u0 = 1.0f / (g_bs[bm] + EPS);
    if (t < 256) { sv[t] = 1.0f; scol[t] = 0.f; }
    for (int i = t; i < 1024; i += 512) su[i] = u0;
    __syncthreads();

    for (int it = 0; it < 5; it++) {
        float vr[8];
#pragma unroll
        for (int j = 0; j < 8; j++) vr[j] = sv[8 * lane + j];
        float c[8] = {0, 0, 0, 0, 0, 0, 0, 0};
        // each warp: 64 rows, 2 at a time (interleaved shfl chains)
        for (int rr = 0; rr < 64; rr += 2) {
            int row = w * 64 + rr;
            uint4 mv0 = *(const uint4*)(Mb + (size_t)row * 256 + 8 * lane);
            uint4 mv1 = *(const uint4*)(Mb + (size_t)(row + 1) * 256 + 8 * lane);
            float m0[8], m1[8];
            {
                float2 f;
                f = __bfloat1622float2(*(__nv_bfloat162*)&mv0.x); m0[0]=f.x; m0[1]=f.y;
                f = __bfloat1622float2(*(__nv_bfloat162*)&mv0.y); m0[2]=f.x; m0[3]=f.y;
                f = __bfloat1622float2(*(__nv_bfloat162*)&mv0.z); m0[4]=f.x; m0[5]=f.y;
                f = __bfloat1622float2(*(__nv_bfloat162*)&mv0.w); m0[6]=f.x; m0[7]=f.y;
                f = __bfloat1622float2(*(__nv_bfloat162*)&mv1.x); m1[0]=f.x; m1[1]=f.y;
                f = __bfloat1622float2(*(__nv_bfloat162*)&mv1.y); m1[2]=f.x; m1[3]=f.y;
                f = __bfloat1622float2(*(__nv_bfloat162*)&mv1.z); m1[4]=f.x; m1[5]=f.y;
                f = __bfloat1622float2(*(__nv_bfloat162*)&mv1.w); m1[6]=f.x; m1[7]=f.y;
            }
            float d0 = 0.f, d1 = 0.f;
#pragma unroll
            for (int j = 0; j < 8; j++) { d0 = fmaf(m0[j], vr[j], d0); d1 = fmaf(m1[j], vr[j], d1); }
#pragma unroll
            for (int o = 16; o; o >>= 1) {
                d0 += __shfl_xor_sync(0xffffffffu, d0, o);
                d1 += __shfl_xor_sync(0xffffffffu, d1, o);
            }
            float uu0 = su[row], uu1 = su[row + 1];
            float un0 = uu0 * TR / (uu0 * d0 + EPS);
            float un1 = uu1 * TR / (uu1 * d1 + EPS);
            if (lane == 0) { su[row] = un0; su[row + 1] = un1; }
#pragma unroll
            for (int j = 0; j < 8; j++)
                c[j] = fmaf(m0[j], un0, fmaf(m1[j], un1, c[j]));
        }
#pragma unroll
        for (int j = 0; j < 8; j++) atomicAdd(&scol[8 * lane + j], c[j]);
        __syncthreads();
        if (t < 256) {
            float v = sv[t], a = scol[t];
            sv[t] = v * TC / (v * a + EPS);
            scol[t] = 0.f;
        }
        __syncthreads();
    }
    if (t < 256) g_v[bm * 256 + t] = sv[t];
    for (int i = t; i < 1024; i += 512) g_u[bm * 1024 + i] = su[i];
}

// ---------------- final row-normalize (fp32 M), write assign, colsums ----------------
__global__ __launch_bounds__(256)
void k_final(float* __restrict__ out) {
    __shared__ float vs[256];
    __shared__ float colacc[256];
    int t = threadIdx.x, lane = t & 31, w = t >> 5;
    int row0 = blockIdx.x * 64;
    int bm = row0 >> 10;
    int mod = row0 >> 14;
    vs[t] = g_v[bm * 256 + t];
    colacc[t] = 0.f;
    __syncthreads();
    float4 vr0 = *(const float4*)&vs[4 * lane];
    float4 vr1 = *(const float4*)&vs[128 + 4 * lane];
    float4 c0 = {0, 0, 0, 0}, c1 = {0, 0, 0, 0};
    float* aout = out + (size_t)(2 + mod) * SEG;
#pragma unroll
    for (int r = 0; r < 8; r++) {
        int n = row0 + w * 8 + r;
        int lrow = n & 16383;
        const float4* Mr = (const float4*)(g_M + (size_t)n * 256);
        float4 m0 = Mr[lane], m1 = Mr[32 + lane];
        float dot = m0.x * vr0.x + m0.y * vr0.y + m0.z * vr0.z + m0.w * vr0.w
                  + m1.x * vr1.x + m1.y * vr1.y + m1.z * vr1.z + m1.w * vr1.w;
#pragma unroll
        for (int o = 16; o; o >>= 1) dot += __shfl_xor_sync(0xffffffffu, dot, o);
        float u = g_u[n];
        float un = u / (u * dot + EPS);
        float4 a0, a1;
        a0.x = m0.x * un * vr0.x; a0.y = m0.y * un * vr0.y;
        a0.z = m0.z * un * vr0.z; a0.w = m0.w * un * vr0.w;
        a1.x = m1.x * un * vr1.x; a1.y = m1.y * un * vr1.y;
        a1.z = m1.z * un * vr1.z; a1.w = m1.w * un * vr1.w;
        *(float4*)(aout + (size_t)lrow * 256 + 4 * lane) = a0;
        *(float4*)(aout + (size_t)lrow * 256 + 128 + 4 * lane) = a1;
        c0.x += a0.x; c0.y += a0.y; c0.z += a0.z; c0.w += a0.w;
        c1.x += a1.x; c1.y += a1.y; c1.z += a1.z; c1.w += a1.w;
    }
    atomicAdd(&colacc[4 * lane + 0], c0.x); atomicAdd(&colacc[4 * lane + 1], c0.y);
    atomicAdd(&colacc[4 * lane + 2], c0.z); atomicAdd(&colacc[4 * lane + 3], c0.w);
    atomicAdd(&colacc[128 + 4 * lane + 0], c1.x); atomicAdd(&colacc[128 + 4 * lane + 1], c1.y);
    atomicAdd(&colacc[128 + 4 * lane + 2], c1.z); atomicAdd(&colacc[128 + 4 * lane + 3], c1.w);
    __syncthreads();
    atomicAdd(&g_csum2[bm * 256 + t], colacc[t]);
}

// ---------------- GEMM2: z = assign @ Phat (+consistency fused into block 0) ----------------
__global__ __launch_bounds__(256, 2)
void k_gemm_z(float* __restrict__ out) {
    int t = threadIdx.x, l = t & 31, w = t >> 5;
    int wm = w >> 1, wn = w & 1;
    int bx = blockIdx.x;
    int row0 = (bx >> 1) * 128;
    int col0 = (bx & 1) * 128;
    int mod = row0 >> 14, lrow0 = row0 & 16383;
    const float* A = out + (size_t)(2 + mod) * SEG + (size_t)lrow0 * 256;
    const __nv_bfloat16* Bh = g_pth + mod * 65536 + (size_t)col0 * 256;
    const __nv_bfloat16* Bl = g_ptl + mod * 65536 + (size_t)col0 * 256;

    float acc[2][8][4];
#pragma unroll
    for (int a = 0; a < 2; a++)
#pragma unroll
        for (int b = 0; b < 8; b++)
#pragma unroll
            for (int d = 0; d < 4; d++) acc[a][b][d] = 0.f;

    mma_mainloop<false>(A, Bh, Bl, acc, t, nullptr);

    float* zb = out + (size_t)mod * SEG;
#pragma unroll
    for (int tm = 0; tm < 2; tm++) {
        int r0 = row0 + wm * 32 + tm * 16 + (l >> 2);
        size_t lr0 = (size_t)(r0 & 16383) * 256, lr1 = lr0 + 8 * 256;
#pragma unroll
        for (int nt = 0; nt < 8; nt++) {
            int col = col0 + wn * 64 + nt * 8 + 2 * (l & 3);
            float* d = acc[tm][nt];
            float2 v0 = {d[0], d[1]}, v1 = {d[2], d[3]};
            *(float2*)(zb + lr0 + col) = v0;
            *(float2*)(zb + lr1 + col) = v1;
        }
    }

    if (bx == 0) {
        __shared__ float red[8];
        float accs = 0.f;
#pragma unroll
        for (int b = 0; b < 16; b++)
            accs += g_csum2[b * 256 + t] * g_csum2[4096 + b * 256 + t];
#pragma unroll
        for (int o = 16; o; o >>= 1) accs += __shfl_xor_sync(0xffffffffu, accs, o);
        if (l == 0) red[w] = accs;
        __syncthreads();
        if (t == 0) {
            float tot = 0.f;
            for (int i = 0; i < 8; i++) tot += red[i];
            float m = tot * (1.0f / 16777216.0f);
            m = fminf(fmaxf(m, 0.f), 1.f);
            out[(size_t)6 * SEG] = 1.0f - m;
        }
    }
}

// ---------------- launch ----------------
extern "C" void kernel_launch(void* const* d_in, const int* in_sizes, int n_in,
                              void* d_out, int out_size) {
    const float* f_rgb = (const float*)d_in[0];
    const float* f_sn  = (const float*)d_in[1];
    const float* p_rgb = (const float*)d_in[2];
    const float* p_sn  = (const float*)d_in[3];
    float* out = (float*)d_out;

    k_proto<<<64, 256>>>(p_rgb, p_sn);
    k_gemm_sim<<<512, 256>>>(f_rgb, f_sn, out);
    k_sinkhorn<<<32, 512>>>();
    k_final<<<512, 256>>>(out);
    k_gemm_z<<<512, 256>>>(out);
}

// round 7
// speedup vs baseline: 1.2747x; 1.2382x over previous
#include <cuda_runtime.h>
#include <cuda_bf16.h>
#include <math.h>
#include <stdint.h>

#define EPS 1e-8f
#define TR  (1.0f/1024.0f)
#define TC  (1.0f/256.0f)
#define SEG 4194304            // 16*1024*256

// ---------------- scratch (device globals; no allocation) ----------------
__device__ __nv_bfloat16 g_Mh[8388608];     // bf16 M for sinkhorn, [32768][256]
__device__ __nv_bfloat16 g_pbh[131072];     // proto normalized, bf16 hi [2][256][256]
__device__ __nv_bfloat16 g_pbl[131072];     // proto normalized, bf16 lo
__device__ __nv_bfloat16 g_pth[131072];     // proto^T hi: [2][d][k]
__device__ __nv_bfloat16 g_ptl[131072];     // proto^T lo
__device__ float g_u[32768];
__device__ float g_v[8192];
__device__ float g_csum2[8192];
__device__ float g_bs[32];

// exp(20*s) via 2^y, FFMA-only
__device__ __forceinline__ float exp20(float s) {
    float y  = s * 28.853900817779268f;
    float fl = floorf(y);
    float f  = y - fl;
    float p = 1.5252733804059840e-05f;
    p = fmaf(p, f, 1.5403530393381609e-04f);
    p = fmaf(p, f, 1.3333558146428443e-03f);
    p = fmaf(p, f, 9.6181291076284772e-03f);
    p = fmaf(p, f, 5.5504108664821580e-02f);
    p = fmaf(p, f, 2.4022650695910071e-01f);
    p = fmaf(p, f, 6.9314718055994531e-01f);
    p = fmaf(p, f, 1.0f);
    int e = (int)fl + 127;
    return p * __int_as_float(e << 23);
}

__device__ __forceinline__ uint32_t smem_u32(const void* p) {
    uint32_t a;
    asm("{ .reg .u64 t; cvta.to.shared.u64 t, %1; cvt.u32.u64 %0, t; }" : "=r"(a) : "l"(p));
    return a;
}
__device__ __forceinline__ void ldmx4(uint32_t* r, uint32_t addr) {
    asm volatile("ldmatrix.sync.aligned.m8n8.x4.shared.b16 {%0,%1,%2,%3}, [%4];"
                 : "=r"(r[0]), "=r"(r[1]), "=r"(r[2]), "=r"(r[3]) : "r"(addr));
}
__device__ __forceinline__ void mma16816(float* d, const uint32_t* a, const uint32_t* b) {
    asm volatile("mma.sync.aligned.m16n8k16.row.col.f32.bf16.bf16.f32 "
                 "{%0,%1,%2,%3}, {%4,%5,%6,%7}, {%8,%9}, {%0,%1,%2,%3};"
                 : "+f"(d[0]), "+f"(d[1]), "+f"(d[2]), "+f"(d[3])
                 : "r"(a[0]), "r"(a[1]), "r"(a[2]), "r"(a[3]), "r"(b[0]), "r"(b[1]));
}
__device__ __forceinline__ uint32_t pack_bf2(__nv_bfloat16 lo, __nv_bfloat16 hi) {
    __nv_bfloat162 t; t.x = lo; t.y = hi;
    uint32_t r; memcpy(&r, &t, 4); return r;
}
__device__ __forceinline__ void split_bf(float x, __nv_bfloat16& h, __nv_bfloat16& l) {
    h = __float2bfloat16_rn(x);
    l = __float2bfloat16_rn(x - __bfloat162float(h));
}
__device__ __forceinline__ uint32_t mapa_u32(uint32_t a, uint32_t r) {
    uint32_t d;
    asm("mapa.shared::cluster.u32 %0, %1, %2;" : "=r"(d) : "r"(a), "r"(r));
    return d;
}
__device__ __forceinline__ float ld_cluster_f32(uint32_t a) {
    float v;
    asm volatile("ld.shared::cluster.b32 %0, [%1];" : "=f"(v) : "r"(a));
    return v;
}
#define CLUSTER_SYNC() do { \
    asm volatile("barrier.cluster.arrive.aligned;" ::: "memory"); \
    asm volatile("barrier.cluster.wait.aligned;"   ::: "memory"); \
} while (0)

// ---------------- setup: zero accumulators + normalize/split/transpose protos ----------------
__global__ void k_proto(const float* __restrict__ p_rgb, const float* __restrict__ p_sn) {
    int gt = blockIdx.x * blockDim.x + threadIdx.x;    // 16384 threads
    if (gt < 8192) g_csum2[gt] = 0.f;
    if (gt < 32)   g_bs[gt] = 0.f;

    int warp = gt >> 5;
    int lane = threadIdx.x & 31;
    int mod = warp >> 8, row = warp & 255;
    const float* src = (mod ? p_sn : p_rgb) + row * 256;
    float v[8], s = 0.f;
#pragma unroll
    for (int j = 0; j < 8; j++) { v[j] = src[lane + 32 * j]; s += v[j] * v[j]; }
#pragma unroll
    for (int o = 16; o; o >>= 1) s += __shfl_xor_sync(0xffffffffu, s, o);
    float inv = 1.0f / (sqrtf(s) + EPS);
    int base = mod * 65536;
#pragma unroll
    for (int j = 0; j < 8; j++) {
        int col = lane + 32 * j;
        float val = v[j] * inv;
        __nv_bfloat16 h, l;
        split_bf(val, h, l);
        g_pbh[base + row * 256 + col] = h;
        g_pbl[base + row * 256 + col] = l;
        g_pth[base + col * 256 + row] = h;
        g_ptl[base + col * 256 + row] = l;
    }
}

// ---------------- GEMM1: sim = Xhat @ Phat^T ; Mh = bf16(exp(20*sim)) (+xnorm fused) ----------------
#define SROW 40

__global__ __launch_bounds__(256, 2)
void k_gemm_sim(const float* __restrict__ f_rgb, const float* __restrict__ f_sn,
                float* __restrict__ out) {
    __shared__ __nv_bfloat16 sAh[128 * SROW], sAl[128 * SROW];
    __shared__ __nv_bfloat16 sBh[128 * SROW], sBl[128 * SROW];
    __shared__ float sSq[128];
    int t = threadIdx.x, l = t & 31, w = t >> 5;
    int wm = w >> 1, wn = w & 1;
    int bx = blockIdx.x;
    int row0 = (bx >> 1) * 128;
    int col0 = (bx & 1) * 128;
    int mod = row0 >> 14, lrow0 = row0 & 16383;
    const float* X = (mod ? f_sn : f_rgb) + (size_t)lrow0 * 256;
    const __nv_bfloat16* Bhp = g_pbh + mod * 65536 + (size_t)col0 * 256;
    const __nv_bfloat16* Blp = g_pbl + mod * 65536 + (size_t)col0 * 256;

    uint32_t baseAh = smem_u32(sAh), baseAl = smem_u32(sAl);
    uint32_t baseBh = smem_u32(sBh), baseBl = smem_u32(sBl);
    uint32_t a_off = (uint32_t)(wm * 32 + (l & 7) + 8 * ((l >> 3) & 1)) * (SROW * 2)
                   + ((l >> 4) & 1) * 16;
    uint32_t b_off = (uint32_t)(wn * 64 + (l & 7) + 8 * ((l >> 4) & 1)) * (SROW * 2)
                   + ((l >> 3) & 1) * 16;

    float acc[2][8][4];
#pragma unroll
    for (int a = 0; a < 2; a++)
#pragma unroll
        for (int b = 0; b < 8; b++)
#pragma unroll
            for (int d = 0; d < 4; d++) acc[a][b][d] = 0.f;

    float ss[4] = {0.f, 0.f, 0.f, 0.f};

    for (int c = 0; c < 8; c++) {
        int dd = c * 32;
#pragma unroll
        for (int i = 0; i < 4; i++) {
            int idx = t + 256 * i;
            int row = idx >> 3, c4 = idx & 7;
            float4 v = *(const float4*)(X + (size_t)row * 256 + dd + 4 * c4);
            ss[i] += v.x * v.x + v.y * v.y + v.z * v.z + v.w * v.w;
            __nv_bfloat16 hx, lx, hy, ly, hz, lz, hw, lw;
            split_bf(v.x, hx, lx); split_bf(v.y, hy, ly);
            split_bf(v.z, hz, lz); split_bf(v.w, hw, lw);
            uint2 ph, pl;
            ph.x = pack_bf2(hx, hy); ph.y = pack_bf2(hz, hw);
            pl.x = pack_bf2(lx, ly); pl.y = pack_bf2(lz, lw);
            int so = row * SROW + 4 * c4;
            *(uint2*)(sAh + so) = ph;
            *(uint2*)(sAl + so) = pl;
        }
#pragma unroll
        for (int i = 0; i < 4; i++) {
            int idx = t + 256 * i;
            int part = idx >> 9, row = (idx >> 2) & 127, c8 = idx & 3;
            const __nv_bfloat16* src = part ? Blp : Bhp;
            uint4 v = *(const uint4*)(src + (size_t)row * 256 + dd + 8 * c8);
            __nv_bfloat16* dst = part ? sBl : sBh;
            *(uint4*)(dst + row * SROW + 8 * c8) = v;
        }
        __syncthreads();
#pragma unroll
        for (int ks = 0; ks < 2; ks++) {
            uint32_t kb = ks * 32;
            uint32_t aH[2][4], aL[2][4];
            ldmx4(aH[0], baseAh + a_off + kb);
            ldmx4(aH[1], baseAh + a_off + 16 * (SROW * 2) + kb);
            ldmx4(aL[0], baseAl + a_off + kb);
            ldmx4(aL[1], baseAl + a_off + 16 * (SROW * 2) + kb);
#pragma unroll
            for (int np = 0; np < 4; np++) {
                uint32_t bo = b_off + (uint32_t)np * 16 * (SROW * 2) + kb;
                uint32_t bH[4], bL[4];
                ldmx4(bH, baseBh + bo);
                ldmx4(bL, baseBl + bo);
#pragma unroll
                for (int tm = 0; tm < 2; tm++) {
                    mma16816(acc[tm][2 * np],     aH[tm], bH);
                    mma16816(acc[tm][2 * np],     aH[tm], bL);
                    mma16816(acc[tm][2 * np],     aL[tm], bH);
                    mma16816(acc[tm][2 * np + 1], aH[tm], bH + 2);
                    mma16816(acc[tm][2 * np + 1], aH[tm], bL + 2);
                    mma16816(acc[tm][2 * np + 1], aL[tm], bH + 2);
                }
            }
        }
        __syncthreads();
    }
#pragma unroll
    for (int i = 0; i < 4; i++) {
        ss[i] += __shfl_xor_sync(0xffffffffu, ss[i], 1);
        ss[i] += __shfl_xor_sync(0xffffffffu, ss[i], 2);
        ss[i] += __shfl_xor_sync(0xffffffffu, ss[i], 4);
    }
    if ((t & 7) == 0) {
#pragma unroll
        for (int i = 0; i < 4; i++)
            sSq[(t >> 3) + 32 * i] = ss[i];
    }
    __syncthreads();

    float* simb = out + (size_t)(4 + mod) * SEG;
    float psum = 0.f;
#pragma unroll
    for (int tm = 0; tm < 2; tm++) {
        int tr0 = wm * 32 + tm * 16 + (l >> 2);
        int r0 = row0 + tr0, r1 = r0 + 8;
        float xi0 = 1.0f / (sqrtf(sSq[tr0]) + EPS);
        float xi1 = 1.0f / (sqrtf(sSq[tr0 + 8]) + EPS);
        size_t lr0 = (size_t)(r0 & 16383) * 256, lr1 = (size_t)(r1 & 16383) * 256;
        size_t gr0 = (size_t)r0 * 256, gr1 = (size_t)r1 * 256;
#pragma unroll
        for (int nt = 0; nt < 8; nt++) {
            int col = col0 + wn * 64 + nt * 8 + 2 * (l & 3);
            float* d = acc[tm][nt];
            float2 s0 = {d[0] * xi0, d[1] * xi0};
            float2 s1 = {d[2] * xi1, d[3] * xi1};
            *(float2*)(simb + lr0 + col) = s0;
            *(float2*)(simb + lr1 + col) = s1;
            float2 e0 = {exp20(s0.x), exp20(s0.y)};
            float2 e1 = {exp20(s1.x), exp20(s1.y)};
            *(uint32_t*)(g_Mh + gr0 + col) = pack_bf2(__float2bfloat16_rn(e0.x),
                                                      __float2bfloat16_rn(e0.y));
            *(uint32_t*)(g_Mh + gr1 + col) = pack_bf2(__float2bfloat16_rn(e1.x),
                                                      __float2bfloat16_rn(e1.y));
            psum += (e0.x + e0.y) + (e1.x + e1.y);
        }
    }
#pragma unroll
    for (int o = 16; o; o >>= 1) psum += __shfl_xor_sync(0xffffffffu, psum, o);
    if (l == 0) atomicAdd(&g_bs[row0 >> 10], psum);
}

// ---------------- sinkhorn: cluster of 4 CTAs per slice, M resident in smem ----------------
// dyn smem: sM 131072 | su 1024 | sv 1024 | scol 1024  = 134144 bytes
#define SINK_SMEM 134144

__global__ void __launch_bounds__(256, 1) __cluster_dims__(4, 1, 1)
k_sinkhorn() {
    extern __shared__ char smraw[];
    __nv_bfloat16* sM = (__nv_bfloat16*)smraw;          // 256 rows x 256 cols
    float* su   = (float*)(smraw + 131072);             // 256
    float* sv   = (float*)(smraw + 132096);             // 256
    float* scol = (float*)(smraw + 133120);             // 256
    int t = threadIdx.x, lane = t & 31, w = t >> 5;     // 8 warps
    uint32_t rank;
    asm("mov.u32 %0, %%cluster_ctarank;" : "=r"(rank));
    int bm = blockIdx.x >> 2;                           // slice 0..31
    uint32_t scol_a = smem_u32(scol);

    // load this CTA's 256-row quarter of the slice (128 KB)
    const uint4* src = (const uint4*)(g_Mh + (size_t)bm * 262144 + (size_t)rank * 65536);
    uint4* dstM = (uint4*)sM;
    for (int i = t; i < 8192; i += 256) dstM[i] = src[i];

    float u0 = 1.0f / (g_bs[bm] + EPS);
    if (t < 256) { su[t] = u0; sv[t] = 1.0f; scol[t] = 0.f; }
    __syncthreads();

    for (int it = 0; it < 5; it++) {
        float vr[8];
#pragma unroll
        for (int j = 0; j < 8; j++) vr[j] = sv[8 * lane + j];
        float c[8] = {0, 0, 0, 0, 0, 0, 0, 0};
        // 8 warps x 32 rows, 2-row interleave
        for (int rr = 0; rr < 32; rr += 2) {
            int row = w * 32 + rr;
            uint4 mv0 = *(const uint4*)(sM + row * 256 + 8 * lane);
            uint4 mv1 = *(const uint4*)(sM + (row + 1) * 256 + 8 * lane);
            float m0[8], m1[8];
            {
                float2 f;
                f = __bfloat1622float2(*(__nv_bfloat162*)&mv0.x); m0[0]=f.x; m0[1]=f.y;
                f = __bfloat1622float2(*(__nv_bfloat162*)&mv0.y); m0[2]=f.x; m0[3]=f.y;
                f = __bfloat1622float2(*(__nv_bfloat162*)&mv0.z); m0[4]=f.x; m0[5]=f.y;
                f = __bfloat1622float2(*(__nv_bfloat162*)&mv0.w); m0[6]=f.x; m0[7]=f.y;
                f = __bfloat1622float2(*(__nv_bfloat162*)&mv1.x); m1[0]=f.x; m1[1]=f.y;
                f = __bfloat1622float2(*(__nv_bfloat162*)&mv1.y); m1[2]=f.x; m1[3]=f.y;
                f = __bfloat1622float2(*(__nv_bfloat162*)&mv1.z); m1[4]=f.x; m1[5]=f.y;
                f = __bfloat1622float2(*(__nv_bfloat162*)&mv1.w); m1[6]=f.x; m1[7]=f.y;
            }
            float d0 = 0.f, d1 = 0.f;
#pragma unroll
            for (int j = 0; j < 8; j++) { d0 = fmaf(m0[j], vr[j], d0); d1 = fmaf(m1[j], vr[j], d1); }
#pragma unroll
            for (int o = 16; o; o >>= 1) {
                d0 += __shfl_xor_sync(0xffffffffu, d0, o);
                d1 += __shfl_xor_sync(0xffffffffu, d1, o);
            }
            float uu0 = su[row], uu1 = su[row + 1];
            float un0 = uu0 * TR / (uu0 * d0 + EPS);
            float un1 = uu1 * TR / (uu1 * d1 + EPS);
            if (lane == 0) { su[row] = un0; su[row + 1] = un1; }
#pragma unroll
            for (int j = 0; j < 8; j++)
                c[j] = fmaf(m0[j], un0, fmaf(m1[j], un1, c[j]));
        }
#pragma unroll
        for (int j = 0; j < 8; j++) atomicAdd(&scol[8 * lane + j], c[j]);
        CLUSTER_SYNC();                      // all CTAs' scol complete & visible
        float tot = 0.f;
        if (t < 256) {
#pragma unroll
            for (uint32_t r = 0; r < 4; r++)
                tot += ld_cluster_f32(mapa_u32(scol_a + 4 * t, r));
        }
        CLUSTER_SYNC();                      // all reads done before zeroing
        if (t < 256) {
            float v = sv[t];
            sv[t] = v * TC / (v * tot + EPS);
            scol[t] = 0.f;
        }
        __syncthreads();
    }
    if (rank == 0 && t < 256) g_v[bm * 256 + t] = sv[t];
    if (t < 256) g_u[bm * 1024 + rank * 256 + t] = su[t];
}

// ---------------- fused: final row-normalize + assign write + z GEMM (N=256 tiles) ----------------
// dyn smem: sAh 10240 | sAl 10240 | sBh 20480 | sBl 20480 | sv 1024 | sun 512 | scol 1024 = 64000
#define FZ_SMEM 64000

__global__ void __launch_bounds__(256, 1)
k_finalz(float* __restrict__ out) {
    extern __shared__ char smraw[];
    __nv_bfloat16* sAh = (__nv_bfloat16*)smraw;
    __nv_bfloat16* sAl = (__nv_bfloat16*)(smraw + 10240);
    __nv_bfloat16* sBh = (__nv_bfloat16*)(smraw + 20480);
    __nv_bfloat16* sBl = (__nv_bfloat16*)(smraw + 40960);
    float* sv   = (float*)(smraw + 61440);
    float* sun  = (float*)(smraw + 62464);
    float* scol = (float*)(smraw + 62976);

    int t = threadIdx.x, l = t & 31, w = t >> 5;
    int row0 = blockIdx.x * 128;
    int bm = row0 >> 10;
    int mod = row0 >> 14, lrow0 = row0 & 16383;
    const float* simb = out + (size_t)(4 + mod) * SEG + (size_t)lrow0 * 256;
    float* ab = out + (size_t)(2 + mod) * SEG + (size_t)lrow0 * 256;

    if (t < 256) { sv[t] = g_v[bm * 256 + t]; scol[t] = 0.f; }
    __syncthreads();

    // ---- phase 1: un per row, assign write, colsums ----
    {
        float vr[8];
#pragma unroll
        for (int j = 0; j < 8; j++) vr[j] = sv[8 * l + j];
        float c[8] = {0, 0, 0, 0, 0, 0, 0, 0};
        for (int rr = 0; rr < 16; rr += 2) {
            int lr = w * 16 + rr;
            float4 s00 = *(const float4*)(simb + (size_t)lr * 256 + 8 * l);
            float4 s01 = *(const float4*)(simb + (size_t)lr * 256 + 8 * l + 4);
            float4 s10 = *(const float4*)(simb + (size_t)(lr + 1) * 256 + 8 * l);
            float4 s11 = *(const float4*)(simb + (size_t)(lr + 1) * 256 + 8 * l + 4);
            float m0[8], m1[8];
            m0[0] = exp20(s00.x); m0[1] = exp20(s00.y); m0[2] = exp20(s00.z); m0[3] = exp20(s00.w);
            m0[4] = exp20(s01.x); m0[5] = exp20(s01.y); m0[6] = exp20(s01.z); m0[7] = exp20(s01.w);
            m1[0] = exp20(s10.x); m1[1] = exp20(s10.y); m1[2] = exp20(s10.z); m1[3] = exp20(s10.w);
            m1[4] = exp20(s11.x); m1[5] = exp20(s11.y); m1[6] = exp20(s11.z); m1[7] = exp20(s11.w);
            float d0 = 0.f, d1 = 0.f;
#pragma unroll
            for (int j = 0; j < 8; j++) { d0 = fmaf(m0[j], vr[j], d0); d1 = fmaf(m1[j], vr[j], d1); }
#pragma unroll
            for (int o = 16; o; o >>= 1) {
                d0 += __shfl_xor_sync(0xffffffffu, d0, o);
                d1 += __shfl_xor_sync(0xffffffffu, d1, o);
            }
            float uu0 = g_u[row0 + lr], uu1 = g_u[row0 + lr + 1];
            float un0 = uu0 / (uu0 * d0 + EPS);
            float un1 = uu1 / (uu1 * d1 + EPS);
            if (l == 0) { sun[lr] = un0; sun[lr + 1] = un1; }
            float a0[8], a1[8];
#pragma unroll
            for (int j = 0; j < 8; j++) {
                a0[j] = m0[j] * un0 * vr[j];
                a1[j] = m1[j] * un1 * vr[j];
                c[j] += a0[j] + a1[j];
            }
            *(float4*)(ab + (size_t)lr * 256 + 8 * l)           = *(float4*)&a0[0];
            *(float4*)(ab + (size_t)lr * 256 + 8 * l + 4)       = *(float4*)&a0[4];
            *(float4*)(ab + (size_t)(lr + 1) * 256 + 8 * l)     = *(float4*)&a1[0];
            *(float4*)(ab + (size_t)(lr + 1) * 256 + 8 * l + 4) = *(float4*)&a1[4];
        }
#pragma unroll
        for (int j = 0; j < 8; j++) atomicAdd(&scol[8 * l + j], c[j]);
        __syncthreads();
        if (t < 256) atomicAdd(&g_csum2[bm * 256 + t], scol[t]);
    }
    __syncthreads();

    // ---- phase 2: z = A @ Phat, A recomputed from sim (L2-hot) ----
    const __nv_bfloat16* Bhp = g_pth + mod * 65536;
    const __nv_bfloat16* Blp = g_ptl + mod * 65536;
    uint32_t baseAh = smem_u32(sAh), baseAl = smem_u32(sAl);
    uint32_t baseBh = smem_u32(sBh), baseBl = smem_u32(sBl);
    int wm = w >> 1, wn = w & 1;
    uint32_t a_off = (uint32_t)(wm * 32 + (l & 7) + 8 * ((l >> 3) & 1)) * (SROW * 2)
                   + ((l >> 4) & 1) * 16;
    uint32_t b_off = (uint32_t)(wn * 128 + (l & 7) + 8 * ((l >> 4) & 1)) * (SROW * 2)
                   + ((l >> 3) & 1) * 16;

    float acc[2][16][4];
#pragma unroll
    for (int a = 0; a < 2; a++)
#pragma unroll
        for (int b = 0; b < 16; b++)
#pragma unroll
            for (int d = 0; d < 4; d++) acc[a][b][d] = 0.f;

    for (int c = 0; c < 8; c++) {
        int dd = c * 32;
#pragma unroll
        for (int i = 0; i < 4; i++) {
            int idx = t + 256 * i;
            int row = idx >> 3, c4 = idx & 7;
            float4 s = *(const float4*)(simb + (size_t)row * 256 + dd + 4 * c4);
            float un_ = sun[row];
            float4 vv = *(const float4*)&sv[dd + 4 * c4];
            float4 av;
            av.x = exp20(s.x) * un_ * vv.x;
            av.y = exp20(s.y) * un_ * vv.y;
            av.z = exp20(s.z) * un_ * vv.z;
            av.w = exp20(s.w) * un_ * vv.w;
            __nv_bfloat16 hx, lx, hy, ly, hz, lz, hw, lw;
            split_bf(av.x, hx, lx); split_bf(av.y, hy, ly);
            split_bf(av.z, hz, lz); split_bf(av.w, hw, lw);
            uint2 ph, pl;
            ph.x = pack_bf2(hx, hy); ph.y = pack_bf2(hz, hw);
            pl.x = pack_bf2(lx, ly); pl.y = pack_bf2(lz, lw);
            int so = row * SROW + 4 * c4;
            *(uint2*)(sAh + so) = ph;
            *(uint2*)(sAl + so) = pl;
        }
#pragma unroll
        for (int i = 0; i < 8; i++) {          // B tile 256 rows x 32 k, 2 parts
            int idx = t + 256 * i;
            int part = idx >> 10, row = (idx >> 2) & 255, c8 = idx & 3;
            const __nv_bfloat16* src = part ? Blp : Bhp;
            uint4 v = *(const uint4*)(src + (size_t)row * 256 + dd + 8 * c8);
            __nv_bfloat16* dst = part ? sBl : sBh;
            *(uint4*)(dst + row * SROW + 8 * c8) = v;
        }
        __syncthreads();
#pragma unroll
        for (int ks = 0; ks < 2; ks++) {
            uint32_t kb = ks * 32;
            uint32_t aH[2][4], aL[2][4];
            ldmx4(aH[0], baseAh + a_off + kb);
            ldmx4(aH[1], baseAh + a_off + 16 * (SROW * 2) + kb);
            ldmx4(aL[0], baseAl + a_off + kb);
            ldmx4(aL[1], baseAl + a_off + 16 * (SROW * 2) + kb);
#pragma unroll
            for (int np = 0; np < 8; np++) {
                uint32_t bo = b_off + (uint32_t)np * 16 * (SROW * 2) + kb;
                uint32_t bH[4], bL[4];
                ldmx4(bH, baseBh + bo);
                ldmx4(bL, baseBl + bo);
#pragma unroll
                for (int tm = 0; tm < 2; tm++) {
                    mma16816(acc[tm][2 * np],     aH[tm], bH);
                    mma16816(acc[tm][2 * np],     aH[tm], bL);
                    mma16816(acc[tm][2 * np],     aL[tm], bH);
                    mma16816(acc[tm][2 * np + 1], aH[tm], bH + 2);
                    mma16816(acc[tm][2 * np + 1], aH[tm], bL + 2);
                    mma16816(acc[tm][2 * np + 1], aL[tm], bH + 2);
                }
            }
        }
        __syncthreads();
    }

    float* zb = out + (size_t)mod * SEG;
#pragma unroll
    for (int tm = 0; tm < 2; tm++) {
        int r0 = row0 + wm * 32 + tm * 16 + (l >> 2);
        size_t lr0 = (size_t)(r0 & 16383) * 256, lr1 = lr0 + 8 * 256;
#pragma unroll
        for (int nt = 0; nt < 16; nt++) {
            int col = wn * 128 + nt * 8 + 2 * (l & 3);
            float* d = acc[tm][nt];
            float2 v0 = {d[0], d[1]}, v1 = {d[2], d[3]};
            *(float2*)(zb + lr0 + col) = v0;
            *(float2*)(zb + lr1 + col) = v1;
        }
    }
}

// ---------------- consistency scalar ----------------
__global__ void k_consist(float* __restrict__ out) {
    __shared__ float red[8];
    int t = threadIdx.x;
    float acc = 0.f;
#pragma unroll
    for (int b = 0; b < 16; b++)
        acc += g_csum2[b * 256 + t] * g_csum2[4096 + b * 256 + t];
#pragma unroll
    for (int o = 16; o; o >>= 1) acc += __shfl_xor_sync(0xffffffffu, acc, o);
    if ((t & 31) == 0) red[t >> 5] = acc;
    __syncthreads();
    if (t == 0) {
        float tot = 0.f;
        for (int i = 0; i < 8; i++) tot += red[i];
        float m = tot * (1.0f / 16777216.0f);
        m = fminf(fmaxf(m, 0.f), 1.f);
        out[(size_t)6 * SEG] = 1.0f - m;
    }
}

// ---------------- launch ----------------
extern "C" void kernel_launch(void* const* d_in, const int* in_sizes, int n_in,
                              void* d_out, int out_size) {
    const float* f_rgb = (const float*)d_in[0];
    const float* f_sn  = (const float*)d_in[1];
    const float* p_rgb = (const float*)d_in[2];
    const float* p_sn  = (const float*)d_in[3];
    float* out = (float*)d_out;

    cudaFuncSetAttribute(k_sinkhorn, cudaFuncAttributeMaxDynamicSharedMemorySize, SINK_SMEM);
    cudaFuncSetAttribute(k_finalz,   cudaFuncAttributeMaxDynamicSharedMemorySize, FZ_SMEM);

    k_proto<<<64, 256>>>(p_rgb, p_sn);
    k_gemm_sim<<<512, 256>>>(f_rgb, f_sn, out);
    k_sinkhorn<<<128, 256, SINK_SMEM>>>();
    k_finalz<<<256, 256, FZ_SMEM>>>(out);
    k_consist<<<1, 256>>>(out);
}